// round 1
// baseline (speedup 1.0000x reference)
#include <cuda_runtime.h>
#include <cuda_bf16.h>
#include <math.h>

// Problem constants (fixed dataset shapes)
#define NMAX 100000
#define GMAX 256
#define HEADS 4

// ---------------- scratch (device globals; no allocation allowed) ----------------
__device__ __align__(16) float g_A[(size_t)NMAX * 128];   // current features
__device__ __align__(16) float g_B[(size_t)NMAX * 128];   // linear output
__device__ __align__(16) float g_C[(size_t)NMAX * 128];   // aggregation buffer
__device__ __align__(16) float g_dis[NMAX];               // deg^-1/2
__device__ __align__(16) float g_ss[NMAX * HEADS];        // attn src scores
__device__ __align__(16) float g_sd[NMAX * HEADS];        // attn dst scores
__device__ __align__(16) float g_m[NMAX * HEADS];         // segment max
__device__ __align__(16) float g_sum[NMAX * HEADS];       // segment sum of exp
__device__ __align__(16) float g_mean[128];
__device__ __align__(16) float g_sq[128];
__device__ __align__(16) float g_scale[128];
__device__ __align__(16) float g_shift[128];
__device__ __align__(16) float g_cnt[GMAX];

__device__ __forceinline__ float lrelu(float v) { return v > 0.f ? v : 0.2f * v; }

__device__ __forceinline__ void atomicMaxFloat(float* addr, float val) {
    if (val >= 0.f) atomicMax((int*)addr, __float_as_int(val));
    else            atomicMin((unsigned int*)addr, __float_as_uint(val));
}

// ---------------- small utility kernels ----------------
__global__ void k_set_val(float* p, float v, int n) {
    int i = blockIdx.x * blockDim.x + threadIdx.x;
    if (i < n) p[i] = v;
}
__global__ void k_zero2(float* a, float* b, int n) {
    int i = blockIdx.x * blockDim.x + threadIdx.x;
    if (i < n) { a[i] = 0.f; b[i] = 0.f; }
}
__global__ void k_deg_count(const int* __restrict__ colp, float* deg, int E) {
    int i = blockIdx.x * blockDim.x + threadIdx.x;
    if (i < E) atomicAdd(&deg[colp[i]], 1.0f);
}
__global__ void k_rsqrt(float* p, int n) {
    int i = blockIdx.x * blockDim.x + threadIdx.x;
    if (i < n) p[i] = rsqrtf(p[i]);
}

// ---------------- tiled linear: H = X @ W ----------------
// W is [DIN, DOUT] row-major. block = 256 threads.
template <int DIN, int DOUT>
__global__ void k_linear(const float* __restrict__ X, const float* __restrict__ W,
                         float* __restrict__ Hout, int n) {
    constexpr int KT  = (DIN > 64) ? 64 : DIN;   // k-tile
    constexpr int TPN = DOUT / 4;                // threads per node
    constexpr int NP  = 256 / TPN;               // nodes per pass
    constexpr int PASSES = 4;
    __shared__ float Ws[KT * DOUT];
    __shared__ float Xs[NP * DIN];
    const int tid = threadIdx.x;
    const int sub = tid / TPN;
    const int cg  = tid % TPN;
    const int base = blockIdx.x * NP * PASSES;

    for (int p = 0; p < PASSES; ++p) {
        int nb = base + p * NP;
        __syncthreads();  // protect Xs from previous pass
        for (int i = tid; i < NP * (DIN / 4); i += 256) {
            int node = nb + i / (DIN / 4);
            float4 v = make_float4(0.f, 0.f, 0.f, 0.f);
            if (node < n) v = ((const float4*)X)[(size_t)node * (DIN / 4) + i % (DIN / 4)];
            ((float4*)Xs)[i] = v;
        }
        float4 acc = make_float4(0.f, 0.f, 0.f, 0.f);
        for (int kt = 0; kt < DIN; kt += KT) {
            __syncthreads();
            for (int i = tid; i < KT * (DOUT / 4); i += 256)
                ((float4*)Ws)[i] = ((const float4*)W)[kt * (DOUT / 4) + i];
            __syncthreads();
#pragma unroll
            for (int k = 0; k < KT; ++k) {
                float xk = Xs[sub * DIN + kt + k];
                float4 w = ((float4*)Ws)[k * TPN + cg];
                acc.x += xk * w.x; acc.y += xk * w.y;
                acc.z += xk * w.z; acc.w += xk * w.w;
            }
        }
        int node = nb + sub;
        if (node < n) ((float4*)Hout)[(size_t)node * TPN + cg] = acc;
    }
}

// ---------------- GCN aggregation ----------------
// init: agg = b + h * dis^2   (self loop folded in)
template <int DOUT>
__global__ void k_gcn_init(const float* __restrict__ h, const float* __restrict__ b,
                           const float* __restrict__ dis, float* __restrict__ agg, int n) {
    constexpr int TPN = DOUT / 4;
    int idx = blockIdx.x * blockDim.x + threadIdx.x;
    if (idx >= n * TPN) return;
    int nn = idx / TPN, cg = idx % TPN;
    float d = dis[nn]; float d2 = d * d;
    float4 hv = ((const float4*)h)[idx];
    float4 bv = ((const float4*)b)[cg];
    float4 o;
    o.x = bv.x + hv.x * d2; o.y = bv.y + hv.y * d2;
    o.z = bv.z + hv.z * d2; o.w = bv.w + hv.w * d2;
    ((float4*)agg)[idx] = o;
}

template <int DOUT>
__global__ void k_gcn_edge(const int* __restrict__ rowp, const int* __restrict__ colp,
                           const float* __restrict__ dis, const float* __restrict__ h,
                           float* __restrict__ agg, int E) {
    constexpr int TPE = DOUT / 4;
    int idx = blockIdx.x * blockDim.x + threadIdx.x;
    if (idx >= E * TPE) return;
    int e = idx / TPE, cg = idx % TPE;
    int r = __ldg(rowp + e), c = __ldg(colp + e);
    float nrm = __ldg(dis + r) * __ldg(dis + c);
    float4 v = __ldg((const float4*)h + (size_t)r * TPE + cg);
    v.x *= nrm; v.y *= nrm; v.z *= nrm; v.w *= nrm;
    atomicAdd((float4*)agg + (size_t)c * TPE + cg, v);
}

// ---------------- BatchNorm ----------------
template <int DOUT>
__global__ void k_bn_partial(const float* __restrict__ src, float* mean, float* sq, int n) {
    constexpr int LPC = 256 / DOUT;   // lanes per column
    constexpr int NPB = 64;           // nodes per block
    int col = threadIdx.x % DOUT, sub = threadIdx.x / DOUT;
    int base = blockIdx.x * NPB;
    int end = base + NPB; if (end > n) end = n;
    float s = 0.f, q = 0.f;
    for (int nn = base + sub; nn < end; nn += LPC) {
        float v = src[(size_t)nn * DOUT + col];
        s += v; q += v * v;
    }
    __shared__ float sh[512];
    sh[threadIdx.x] = s; sh[256 + threadIdx.x] = q;
    __syncthreads();
    if (sub == 0) {
        for (int k = 1; k < LPC; ++k) { s += sh[k * DOUT + col]; q += sh[256 + k * DOUT + col]; }
        atomicAdd(mean + col, s);
        atomicAdd(sq + col, q);
    }
}

template <int DOUT>
__global__ void k_bn_final(const float* mean, const float* sq,
                           const float* __restrict__ g, const float* __restrict__ b,
                           float* scale, float* shift, int n) {
    int c = threadIdx.x;
    if (c >= DOUT) return;
    float inv = 1.0f / (float)n;
    float mu = mean[c] * inv;
    float var = sq[c] * inv - mu * mu;
    float sc = g[c] * rsqrtf(var + 1e-5f);
    scale[c] = sc;
    shift[c] = b[c] - mu * sc;
}

template <int DOUT, bool RELU>
__global__ void k_bn_apply(const float* __restrict__ src, const float* scale,
                           const float* shift, float* __restrict__ dst, int n) {
    constexpr int TPN = DOUT / 4;
    int idx = blockIdx.x * blockDim.x + threadIdx.x;
    if (idx >= n * TPN) return;
    int cg = idx % TPN;
    float4 v = ((const float4*)src)[idx];
    float4 sc = ((const float4*)scale)[cg];
    float4 sh = ((const float4*)shift)[cg];
    v.x = v.x * sc.x + sh.x; v.y = v.y * sc.y + sh.y;
    v.z = v.z * sc.z + sh.z; v.w = v.w * sc.w + sh.w;
    if (RELU) { v.x = lrelu(v.x); v.y = lrelu(v.y); v.z = lrelu(v.z); v.w = lrelu(v.w); }
    ((float4*)dst)[idx] = v;
}

// ---------------- GAT ----------------
// per-node attention scores: ss[n,h] = <h2[n,h,:], a_src[h,:]>, sd likewise
template <int D, int H>
__global__ void k_gat_scores(const float* __restrict__ h2,
                             const float* __restrict__ a_src, const float* __restrict__ a_dst,
                             float* __restrict__ ss, float* __restrict__ sd, int n) {
    constexpr int C  = D / H;
    constexpr int L  = D / 4;   // active lanes
    constexpr int GP = C / 4;   // lanes per head
    int warp = (blockIdx.x * blockDim.x + threadIdx.x) >> 5;
    int lane = threadIdx.x & 31;
    if (warp >= n) return;
    float ps = 0.f, pd = 0.f;
    int head = 0;
    if (lane < L) {
        float4 v = ((const float4*)h2)[(size_t)warp * L + lane];
        head = lane / GP;
        int o = head * C + (lane % GP) * 4;
        ps = v.x * __ldg(a_src + o) + v.y * __ldg(a_src + o + 1)
           + v.z * __ldg(a_src + o + 2) + v.w * __ldg(a_src + o + 3);
        pd = v.x * __ldg(a_dst + o) + v.y * __ldg(a_dst + o + 1)
           + v.z * __ldg(a_dst + o + 2) + v.w * __ldg(a_dst + o + 3);
    }
#pragma unroll
    for (int off = GP / 2; off > 0; off >>= 1) {
        ps += __shfl_xor_sync(0xffffffff, ps, off);
        pd += __shfl_xor_sync(0xffffffff, pd, off);
    }
    if (lane < L && (lane % GP) == 0) {
        ss[(size_t)warp * H + head] = ps;
        sd[(size_t)warp * H + head] = pd;
    }
}

__global__ void k_attn_reset(float* m, float* s, int total) {
    int i = blockIdx.x * blockDim.x + threadIdx.x;
    if (i < total) { m[i] = -INFINITY; s[i] = 0.f; }
}

// segment max over edges (incl. self loops, idx >= E -> r=c=idx-E)
template <int H>
__global__ void k_gat_max(const int* __restrict__ rowp, const int* __restrict__ colp,
                          const float* __restrict__ ss, const float* __restrict__ sd,
                          float* m, int E, int n) {
    int idx = blockIdx.x * blockDim.x + threadIdx.x;
    int total = (E + n) * H;
    if (idx >= total) return;
    int e = idx / H, h = idx % H;
    int r, c;
    if (e < E) { r = __ldg(rowp + e); c = __ldg(colp + e); } else { r = c = e - E; }
    float v = lrelu(__ldg(ss + (size_t)r * H + h) + __ldg(sd + (size_t)c * H + h));
    atomicMaxFloat(&m[(size_t)c * H + h], v);
}

template <int H>
__global__ void k_gat_sum(const int* __restrict__ rowp, const int* __restrict__ colp,
                          const float* __restrict__ ss, const float* __restrict__ sd,
                          const float* __restrict__ m, float* s, int E, int n) {
    int idx = blockIdx.x * blockDim.x + threadIdx.x;
    int total = (E + n) * H;
    if (idx >= total) return;
    int e = idx / H, h = idx % H;
    int r, c;
    if (e < E) { r = __ldg(rowp + e); c = __ldg(colp + e); } else { r = c = e - E; }
    float v = lrelu(__ldg(ss + (size_t)r * H + h) + __ldg(sd + (size_t)c * H + h));
    float ex = __expf(v - __ldg(m + (size_t)c * H + h));
    atomicAdd(&s[(size_t)c * H + h], ex);
}

// init agg for GAT with residual + bias: agg = b + x
template <int DOUT>
__global__ void k_gat_init(const float* __restrict__ b, const float* __restrict__ x,
                           float* __restrict__ agg, int n) {
    constexpr int TPN = DOUT / 4;
    int idx = blockIdx.x * blockDim.x + threadIdx.x;
    if (idx >= n * TPN) return;
    int cg = idx % TPN;
    float4 xv = ((const float4*)x)[idx];
    float4 bv = ((const float4*)b)[cg];
    xv.x += bv.x; xv.y += bv.y; xv.z += bv.z; xv.w += bv.w;
    ((float4*)agg)[idx] = xv;
}

template <int DOUT, int H>
__global__ void k_gat_agg(const int* __restrict__ rowp, const int* __restrict__ colp,
                          const float* __restrict__ ss, const float* __restrict__ sd,
                          const float* __restrict__ m, const float* __restrict__ ssum,
                          const float* __restrict__ h2, float* __restrict__ agg,
                          int E, int n) {
    constexpr int TPE = DOUT / 4;
    constexpr int C = DOUT / H;
    int idx = blockIdx.x * blockDim.x + threadIdx.x;
    int total = (E + n) * TPE;
    if (idx >= total) return;
    int e = idx / TPE, cg = idx % TPE;
    int r, c;
    if (e < E) { r = __ldg(rowp + e); c = __ldg(colp + e); } else { r = c = e - E; }
    int head = (cg * 4) / C;
    float eV = lrelu(__ldg(ss + (size_t)r * H + head) + __ldg(sd + (size_t)c * H + head));
    float alpha = __expf(eV - __ldg(m + (size_t)c * H + head)) / __ldg(ssum + (size_t)c * H + head);
    float4 v = __ldg((const float4*)h2 + (size_t)r * TPE + cg);
    v.x *= alpha; v.y *= alpha; v.z *= alpha; v.w *= alpha;
    atomicAdd((float4*)agg + (size_t)c * TPE + cg, v);
}

template <int DOUT>
__global__ void k_lrelu_copy(const float* __restrict__ src, float* __restrict__ dst, int n) {
    constexpr int TPN = DOUT / 4;
    int idx = blockIdx.x * blockDim.x + threadIdx.x;
    if (idx >= n * TPN) return;
    float4 v = ((const float4*)src)[idx];
    v.x = lrelu(v.x); v.y = lrelu(v.y); v.z = lrelu(v.z); v.w = lrelu(v.w);
    ((float4*)dst)[idx] = v;
}

// ---------------- pooling ----------------
__global__ void k_pool_sum(const float* __restrict__ x, const int* __restrict__ batch,
                           float* __restrict__ out, int n) {
    int idx = blockIdx.x * blockDim.x + threadIdx.x;
    if (idx >= n * 16) return;
    int nn = idx / 16, cg = idx % 16;
    int g = __ldg(batch + nn);
    float4 v = ((const float4*)x)[idx];
    atomicAdd((float4*)out + (size_t)g * 16 + cg, v);
}
__global__ void k_pool_cnt(const int* __restrict__ batch, float* cnt, int n) {
    int i = blockIdx.x * blockDim.x + threadIdx.x;
    if (i < n) atomicAdd(&cnt[batch[i]], 1.0f);
}
__global__ void k_pool_div(float* out, const float* cnt, int total) {
    int i = blockIdx.x * blockDim.x + threadIdx.x;
    if (i >= total) return;
    int g = i / 64;
    out[i] /= fmaxf(cnt[g], 1.0f);
}

// ---------------- host ----------------
static inline int GRID(long long t) { return (int)((t + 255) / 256); }

extern "C" void kernel_launch(void* const* d_in, const int* in_sizes, int n_in,
                              void* d_out, int out_size) {
    const float* x     = (const float*)d_in[0];
    const int*   ei    = (const int*)d_in[1];
    const int*   batch = (const int*)d_in[2];
    const int n = in_sizes[0] / 16;
    const int E = in_sizes[1] / 2;
    const int* rowp = ei;
    const int* colp = ei + E;

    const float* gcn_w[4] = {(const float*)d_in[3], (const float*)d_in[7],
                             (const float*)d_in[11], (const float*)d_in[15]};
    const float* gcn_b[4] = {(const float*)d_in[4], (const float*)d_in[8],
                             (const float*)d_in[12], (const float*)d_in[16]};
    const float* bn_g[4]  = {(const float*)d_in[5], (const float*)d_in[9],
                             (const float*)d_in[13], (const float*)d_in[17]};
    const float* bn_b[4]  = {(const float*)d_in[6], (const float*)d_in[10],
                             (const float*)d_in[14], (const float*)d_in[18]};
    const float* gat_w0    = (const float*)d_in[19];
    const float* gat_asrc0 = (const float*)d_in[20];
    const float* gat_adst0 = (const float*)d_in[21];
    const float* gat_b0    = (const float*)d_in[22];
    const float* gat_w2    = (const float*)d_in[23];
    const float* gat_asrc2 = (const float*)d_in[24];
    const float* gat_adst2 = (const float*)d_in[25];
    const float* gat_b2    = (const float*)d_in[26];

    float *A, *B, *C, *dis, *ss, *sd, *m, *sm, *mean, *sq, *scale, *shift, *cnt;
    cudaGetSymbolAddress((void**)&A, g_A);
    cudaGetSymbolAddress((void**)&B, g_B);
    cudaGetSymbolAddress((void**)&C, g_C);
    cudaGetSymbolAddress((void**)&dis, g_dis);
    cudaGetSymbolAddress((void**)&ss, g_ss);
    cudaGetSymbolAddress((void**)&sd, g_sd);
    cudaGetSymbolAddress((void**)&m, g_m);
    cudaGetSymbolAddress((void**)&sm, g_sum);
    cudaGetSymbolAddress((void**)&mean, g_mean);
    cudaGetSymbolAddress((void**)&sq, g_sq);
    cudaGetSymbolAddress((void**)&scale, g_scale);
    cudaGetSymbolAddress((void**)&shift, g_shift);
    cudaGetSymbolAddress((void**)&cnt, g_cnt);
    float* out = (float*)d_out;

    // degrees with self loops: deg = 1 + in-degree; dis = rsqrt(deg)
    k_set_val<<<GRID(n), 256>>>(dis, 1.0f, n);
    k_deg_count<<<GRID(E), 256>>>(colp, dis, E);
    k_rsqrt<<<GRID(n), 256>>>(dis, n);

    // ----- layer 0: GCN 16->64, BN, GAT(64,H=4,C=16)+residual, lrelu -----
    k_linear<16, 64><<<(n + 63) / 64, 256>>>(x, gcn_w[0], B, n);
    k_gcn_init<64><<<GRID((long long)n * 16), 256>>>(B, gcn_b[0], dis, C, n);
    k_gcn_edge<64><<<GRID((long long)E * 16), 256>>>(rowp, colp, dis, B, C, E);
    k_zero2<<<1, 128>>>(mean, sq, 128);
    k_bn_partial<64><<<(n + 63) / 64, 256>>>(C, mean, sq, n);
    k_bn_final<64><<<1, 64>>>(mean, sq, bn_g[0], bn_b[0], scale, shift, n);
    k_bn_apply<64, false><<<GRID((long long)n * 16), 256>>>(C, scale, shift, A, n);
    k_linear<64, 64><<<(n + 63) / 64, 256>>>(A, gat_w0, B, n);
    k_gat_scores<64, 4><<<(n + 3) / 4, 128>>>(B, gat_asrc0, gat_adst0, ss, sd, n);
    k_attn_reset<<<GRID((long long)n * 4), 256>>>(m, sm, n * 4);
    k_gat_max<4><<<GRID((long long)(E + n) * 4), 256>>>(rowp, colp, ss, sd, m, E, n);
    k_gat_sum<4><<<GRID((long long)(E + n) * 4), 256>>>(rowp, colp, ss, sd, m, sm, E, n);
    k_gat_init<64><<<GRID((long long)n * 16), 256>>>(gat_b0, A, C, n);
    k_gat_agg<64, 4><<<GRID((long long)(E + n) * 16), 256>>>(rowp, colp, ss, sd, m, sm, B, C, E, n);
    k_lrelu_copy<64><<<GRID((long long)n * 16), 256>>>(C, A, n);

    // ----- layer 1: GCN 64->128, BN, lrelu -----
    k_linear<64, 128><<<(n + 31) / 32, 256>>>(A, gcn_w[1], B, n);
    k_gcn_init<128><<<GRID((long long)n * 32), 256>>>(B, gcn_b[1], dis, C, n);
    k_gcn_edge<128><<<GRID((long long)E * 32), 256>>>(rowp, colp, dis, B, C, E);
    k_zero2<<<1, 128>>>(mean, sq, 128);
    k_bn_partial<128><<<(n + 63) / 64, 256>>>(C, mean, sq, n);
    k_bn_final<128><<<1, 128>>>(mean, sq, bn_g[1], bn_b[1], scale, shift, n);
    k_bn_apply<128, true><<<GRID((long long)n * 32), 256>>>(C, scale, shift, A, n);

    // ----- layer 2: GCN 128->128, BN, GAT(128,H=4,C=32)+residual, lrelu -----
    k_linear<128, 128><<<(n + 31) / 32, 256>>>(A, gcn_w[2], B, n);
    k_gcn_init<128><<<GRID((long long)n * 32), 256>>>(B, gcn_b[2], dis, C, n);
    k_gcn_edge<128><<<GRID((long long)E * 32), 256>>>(rowp, colp, dis, B, C, E);
    k_zero2<<<1, 128>>>(mean, sq, 128);
    k_bn_partial<128><<<(n + 63) / 64, 256>>>(C, mean, sq, n);
    k_bn_final<128><<<1, 128>>>(mean, sq, bn_g[2], bn_b[2], scale, shift, n);
    k_bn_apply<128, false><<<GRID((long long)n * 32), 256>>>(C, scale, shift, A, n);
    k_linear<128, 128><<<(n + 31) / 32, 256>>>(A, gat_w2, B, n);
    k_gat_scores<128, 4><<<(n + 3) / 4, 128>>>(B, gat_asrc2, gat_adst2, ss, sd, n);
    k_attn_reset<<<GRID((long long)n * 4), 256>>>(m, sm, n * 4);
    k_gat_max<4><<<GRID((long long)(E + n) * 4), 256>>>(rowp, colp, ss, sd, m, E, n);
    k_gat_sum<4><<<GRID((long long)(E + n) * 4), 256>>>(rowp, colp, ss, sd, m, sm, E, n);
    k_gat_init<128><<<GRID((long long)n * 32), 256>>>(gat_b2, A, C, n);
    k_gat_agg<128, 4><<<GRID((long long)(E + n) * 32), 256>>>(rowp, colp, ss, sd, m, sm, B, C, E, n);
    k_lrelu_copy<128><<<GRID((long long)n * 32), 256>>>(C, A, n);

    // ----- layer 3: GCN 128->64, BN (no relu, no GAT) -----
    k_linear<128, 64><<<(n + 63) / 64, 256>>>(A, gcn_w[3], B, n);
    k_gcn_init<64><<<GRID((long long)n * 16), 256>>>(B, gcn_b[3], dis, C, n);
    k_gcn_edge<64><<<GRID((long long)E * 16), 256>>>(rowp, colp, dis, B, C, E);
    k_zero2<<<1, 128>>>(mean, sq, 128);
    k_bn_partial<64><<<(n + 63) / 64, 256>>>(C, mean, sq, n);
    k_bn_final<64><<<1, 64>>>(mean, sq, bn_g[3], bn_b[3], scale, shift, n);
    k_bn_apply<64, false><<<GRID((long long)n * 16), 256>>>(C, scale, shift, A, n);

    // ----- global mean pool -----
    const int G = out_size / 64;
    k_set_val<<<GRID(out_size), 256>>>(out, 0.0f, out_size);
    k_set_val<<<GRID(G), 256>>>(cnt, 0.0f, G);
    k_pool_sum<<<GRID((long long)n * 16), 256>>>(A, batch, out, n);
    k_pool_cnt<<<GRID(n), 256>>>(batch, cnt, n);
    k_pool_div<<<GRID(out_size), 256>>>(out, cnt, out_size);
}

// round 2
// speedup vs baseline: 1.6066x; 1.6066x over previous
#include <cuda_runtime.h>
#include <cuda_bf16.h>
#include <math.h>

// Problem constants (fixed dataset shapes)
#define NMAX 100000
#define EMAX 1600000
#define GMAX 256
#define HEADS 4
#define SCAN_CHUNK 512

// ---------------- scratch (device globals; no allocation allowed) ----------------
__device__ __align__(16) float g_A[(size_t)NMAX * 128];   // current features
__device__ __align__(16) float g_B[(size_t)NMAX * 128];   // linear output
__device__ __align__(16) float g_C[(size_t)NMAX * 128];   // aggregation buffer
__device__ __align__(16) float g_dis[NMAX];               // deg^-1/2
__device__ __align__(16) int   g_deg[NMAX];
__device__ __align__(16) int   g_rowptr[NMAX + 1];
__device__ __align__(16) int   g_cursor[NMAX];
__device__ __align__(16) int   g_csr[EMAX];               // source node per CSR slot
__device__ __align__(16) int   g_blksum[1024];
__device__ __align__(16) float g_ss[NMAX * HEADS];        // attn src scores
__device__ __align__(16) float g_sd[NMAX * HEADS];        // attn dst scores
__device__ __align__(16) float g_mean[128];
__device__ __align__(16) float g_sq[128];
__device__ __align__(16) float g_scale[128];
__device__ __align__(16) float g_shift[128];
__device__ __align__(16) float g_cnt[GMAX];

__device__ __forceinline__ float lrelu(float v) { return v > 0.f ? v : 0.2f * v; }

// ---------------- small utility kernels ----------------
__global__ void k_set_val(float* p, float v, int n) {
    int i = blockIdx.x * blockDim.x + threadIdx.x;
    if (i < n) p[i] = v;
}
__global__ void k_zero2(float* a, float* b, int n) {
    int i = blockIdx.x * blockDim.x + threadIdx.x;
    if (i < n) { a[i] = 0.f; b[i] = 0.f; }
}
__global__ void k_deg_zero(int* deg, int n) {
    int i = blockIdx.x * blockDim.x + threadIdx.x;
    if (i < n) deg[i] = 0;
}
__global__ void k_deg_count(const int* __restrict__ colp, int* deg, int E) {
    int i = blockIdx.x * blockDim.x + threadIdx.x;
    if (i < E) atomicAdd(&deg[colp[i]], 1);
}
__global__ void k_dis(const int* __restrict__ deg, float* dis, int n) {
    int i = blockIdx.x * blockDim.x + threadIdx.x;
    if (i < n) dis[i] = rsqrtf(1.0f + (float)deg[i]);
}

// ---------------- scan (exclusive prefix sum of deg -> rowptr) ----------------
__global__ void k_scan1(const int* __restrict__ deg, int* blksum, int n) {
    __shared__ int sh[SCAN_CHUNK];
    int i = blockIdx.x * SCAN_CHUNK + threadIdx.x;
    sh[threadIdx.x] = (i < n) ? deg[i] : 0;
    __syncthreads();
    for (int off = SCAN_CHUNK / 2; off > 0; off >>= 1) {
        if (threadIdx.x < off) sh[threadIdx.x] += sh[threadIdx.x + off];
        __syncthreads();
    }
    if (threadIdx.x == 0) blksum[blockIdx.x] = sh[0];
}
__global__ void k_scan2(int* blksum, int nb, int* rowptr_n) {
    if (threadIdx.x == 0) {
        int acc = 0;
        for (int b = 0; b < nb; ++b) {
            int v = blksum[b];
            blksum[b] = acc;
            acc += v;
        }
        *rowptr_n = acc;   // rowptr[n] = E
    }
}
__global__ void k_scan3(const int* __restrict__ deg, const int* __restrict__ blksum,
                        int* rowptr, int* cursor, int n) {
    __shared__ int sh[SCAN_CHUNK];
    int i = blockIdx.x * SCAN_CHUNK + threadIdx.x;
    int v = (i < n) ? deg[i] : 0;
    sh[threadIdx.x] = v;
    __syncthreads();
    // Hillis-Steele inclusive scan
    for (int off = 1; off < SCAN_CHUNK; off <<= 1) {
        int t = (threadIdx.x >= off) ? sh[threadIdx.x - off] : 0;
        __syncthreads();
        sh[threadIdx.x] += t;
        __syncthreads();
    }
    if (i < n) {
        int excl = blksum[blockIdx.x] + sh[threadIdx.x] - v;
        rowptr[i] = excl;
        cursor[i] = excl;
    }
}
__global__ void k_csr_fill(const int* __restrict__ rowp, const int* __restrict__ colp,
                           int* cursor, int* csr, int E) {
    int e = blockIdx.x * blockDim.x + threadIdx.x;
    if (e >= E) return;
    int c = colp[e];
    int pos = atomicAdd(&cursor[c], 1);
    csr[pos] = rowp[e];
}

// ---------------- tiled linear: H = X @ W ----------------
template <int DIN, int DOUT>
__global__ void k_linear(const float* __restrict__ X, const float* __restrict__ W,
                         float* __restrict__ Hout, int n) {
    constexpr int KT  = (DIN > 64) ? 64 : DIN;   // k-tile
    constexpr int TPN = DOUT / 4;                // threads per node
    constexpr int NP  = 256 / TPN;               // nodes per pass
    constexpr int PASSES = 4;
    __shared__ float Ws[KT * DOUT];
    __shared__ float Xs[NP * DIN];
    const int tid = threadIdx.x;
    const int sub = tid / TPN;
    const int cg  = tid % TPN;
    const int base = blockIdx.x * NP * PASSES;

    for (int p = 0; p < PASSES; ++p) {
        int nb = base + p * NP;
        __syncthreads();
        for (int i = tid; i < NP * (DIN / 4); i += 256) {
            int node = nb + i / (DIN / 4);
            float4 v = make_float4(0.f, 0.f, 0.f, 0.f);
            if (node < n) v = ((const float4*)X)[(size_t)node * (DIN / 4) + i % (DIN / 4)];
            ((float4*)Xs)[i] = v;
        }
        float4 acc = make_float4(0.f, 0.f, 0.f, 0.f);
        for (int kt = 0; kt < DIN; kt += KT) {
            __syncthreads();
            for (int i = tid; i < KT * (DOUT / 4); i += 256)
                ((float4*)Ws)[i] = ((const float4*)W)[kt * (DOUT / 4) + i];
            __syncthreads();
#pragma unroll
            for (int k = 0; k < KT; ++k) {
                float xk = Xs[sub * DIN + kt + k];
                float4 w = ((float4*)Ws)[k * TPN + cg];
                acc.x += xk * w.x; acc.y += xk * w.y;
                acc.z += xk * w.z; acc.w += xk * w.w;
            }
        }
        int node = nb + sub;
        if (node < n) ((float4*)Hout)[(size_t)node * TPN + cg] = acc;
    }
}

// ---------------- GCN aggregation: CSR gather (atomic-free) ----------------
// out[c] = b + h[c]*dis[c]^2 + sum_{r in N(c)} h[r]*dis[r]*dis[c]
template <int DOUT>
__global__ void k_gcn_gather(const int* __restrict__ rowptr, const int* __restrict__ csr,
                             const float* __restrict__ dis, const float* __restrict__ h,
                             const float* __restrict__ b, float* __restrict__ out, int n) {
    constexpr int TPN = DOUT / 4;
    constexpr int GPB = 256 / TPN;
    int node = blockIdx.x * GPB + threadIdx.x / TPN;
    int cg = threadIdx.x % TPN;
    if (node >= n) return;
    float dc = __ldg(dis + node);
    float4 acc = __ldg((const float4*)b + cg);
    {
        float4 hv = __ldg((const float4*)h + (size_t)node * TPN + cg);
        float w = dc * dc;
        acc.x += hv.x * w; acc.y += hv.y * w; acc.z += hv.z * w; acc.w += hv.w * w;
    }
    int s0 = __ldg(rowptr + node), s1 = __ldg(rowptr + node + 1);
    for (int j = s0; j < s1; ++j) {
        int r = __ldg(csr + j);
        float w = __ldg(dis + r) * dc;
        float4 v = __ldg((const float4*)h + (size_t)r * TPN + cg);
        acc.x += v.x * w; acc.y += v.y * w; acc.z += v.z * w; acc.w += v.w * w;
    }
    ((float4*)out)[(size_t)node * TPN + cg] = acc;
}

// ---------------- BatchNorm ----------------
template <int DOUT>
__global__ void k_bn_partial(const float* __restrict__ src, float* mean, float* sq, int n) {
    constexpr int LPC = 256 / DOUT;
    constexpr int NPB = 64;
    int col = threadIdx.x % DOUT, sub = threadIdx.x / DOUT;
    int base = blockIdx.x * NPB;
    int end = base + NPB; if (end > n) end = n;
    float s = 0.f, q = 0.f;
    for (int nn = base + sub; nn < end; nn += LPC) {
        float v = src[(size_t)nn * DOUT + col];
        s += v; q += v * v;
    }
    __shared__ float sh[512];
    sh[threadIdx.x] = s; sh[256 + threadIdx.x] = q;
    __syncthreads();
    if (sub == 0) {
        for (int k = 1; k < LPC; ++k) { s += sh[k * DOUT + col]; q += sh[256 + k * DOUT + col]; }
        atomicAdd(mean + col, s);
        atomicAdd(sq + col, q);
    }
}

template <int DOUT>
__global__ void k_bn_final(const float* mean, const float* sq,
                           const float* __restrict__ g, const float* __restrict__ b,
                           float* scale, float* shift, int n) {
    int c = threadIdx.x;
    if (c >= DOUT) return;
    float inv = 1.0f / (float)n;
    float mu = mean[c] * inv;
    float var = sq[c] * inv - mu * mu;
    float sc = g[c] * rsqrtf(var + 1e-5f);
    scale[c] = sc;
    shift[c] = b[c] - mu * sc;
}

template <int DOUT, bool RELU>
__global__ void k_bn_apply(const float* __restrict__ src, const float* scale,
                           const float* shift, float* __restrict__ dst, int n) {
    constexpr int TPN = DOUT / 4;
    int idx = blockIdx.x * blockDim.x + threadIdx.x;
    if (idx >= n * TPN) return;
    int cg = idx % TPN;
    float4 v = ((const float4*)src)[idx];
    float4 sc = ((const float4*)scale)[cg];
    float4 sh = ((const float4*)shift)[cg];
    v.x = v.x * sc.x + sh.x; v.y = v.y * sc.y + sh.y;
    v.z = v.z * sc.z + sh.z; v.w = v.w * sc.w + sh.w;
    if (RELU) { v.x = lrelu(v.x); v.y = lrelu(v.y); v.z = lrelu(v.z); v.w = lrelu(v.w); }
    ((float4*)dst)[idx] = v;
}

// ---------------- GAT ----------------
template <int D, int H>
__global__ void k_gat_scores(const float* __restrict__ h2,
                             const float* __restrict__ a_src, const float* __restrict__ a_dst,
                             float* __restrict__ ss, float* __restrict__ sd, int n) {
    constexpr int C  = D / H;
    constexpr int L  = D / 4;   // active lanes
    constexpr int GP = C / 4;   // lanes per head
    int warp = (blockIdx.x * blockDim.x + threadIdx.x) >> 5;
    int lane = threadIdx.x & 31;
    if (warp >= n) return;
    float ps = 0.f, pd = 0.f;
    int head = 0;
    if (lane < L) {
        float4 v = ((const float4*)h2)[(size_t)warp * L + lane];
        head = lane / GP;
        int o = head * C + (lane % GP) * 4;
        ps = v.x * __ldg(a_src + o) + v.y * __ldg(a_src + o + 1)
           + v.z * __ldg(a_src + o + 2) + v.w * __ldg(a_src + o + 3);
        pd = v.x * __ldg(a_dst + o) + v.y * __ldg(a_dst + o + 1)
           + v.z * __ldg(a_dst + o + 2) + v.w * __ldg(a_dst + o + 3);
    }
#pragma unroll
    for (int off = GP / 2; off > 0; off >>= 1) {
        ps += __shfl_xor_sync(0xffffffff, ps, off);
        pd += __shfl_xor_sync(0xffffffff, pd, off);
    }
    if (lane < L && (lane % GP) == 0) {
        ss[(size_t)warp * H + head] = ps;
        sd[(size_t)warp * H + head] = pd;
    }
}

// Fully fused GAT: segment softmax + weighted gather + bias + residual (+lrelu)
// Replaces reset/max/sum/init/agg/lrelu (6 kernels -> 1), atomic-free.
template <int DOUT, int H, bool RELU>
__global__ void k_gat_fused(const int* __restrict__ rowptr, const int* __restrict__ csr,
                            const float* __restrict__ ss, const float* __restrict__ sd,
                            const float* __restrict__ h2, const float* __restrict__ bias,
                            const float* __restrict__ xres, float* __restrict__ out, int n) {
    constexpr int TPN = DOUT / 4;
    constexpr int GPB = 256 / TPN;
    constexpr int C = DOUT / H;
    int node = blockIdx.x * GPB + threadIdx.x / TPN;
    int cg = threadIdx.x % TPN;
    if (node >= n) return;
    int head = (cg * 4) / C;
    float sdv = __ldg(sd + (size_t)node * H + head);
    int s0 = __ldg(rowptr + node), s1 = __ldg(rowptr + node + 1);

    // pass 1: segment max (incl. self loop)
    float eself = lrelu(__ldg(ss + (size_t)node * H + head) + sdv);
    float m = eself;
    for (int j = s0; j < s1; ++j) {
        int r = __ldg(csr + j);
        float e = lrelu(__ldg(ss + (size_t)r * H + head) + sdv);
        m = fmaxf(m, e);
    }
    // pass 2: exp-sum + weighted feature gather
    float wsum = __expf(eself - m);
    float4 acc = __ldg((const float4*)h2 + (size_t)node * TPN + cg);
    acc.x *= wsum; acc.y *= wsum; acc.z *= wsum; acc.w *= wsum;
    for (int j = s0; j < s1; ++j) {
        int r = __ldg(csr + j);
        float e = lrelu(__ldg(ss + (size_t)r * H + head) + sdv);
        float w = __expf(e - m);
        wsum += w;
        float4 v = __ldg((const float4*)h2 + (size_t)r * TPN + cg);
        acc.x += v.x * w; acc.y += v.y * w; acc.z += v.z * w; acc.w += v.w * w;
    }
    float inv = 1.0f / wsum;
    float4 bv = __ldg((const float4*)bias + cg);
    float4 xv = __ldg((const float4*)xres + (size_t)node * TPN + cg);
    float4 o;
    o.x = acc.x * inv + bv.x + xv.x;
    o.y = acc.y * inv + bv.y + xv.y;
    o.z = acc.z * inv + bv.z + xv.z;
    o.w = acc.w * inv + bv.w + xv.w;
    if (RELU) { o.x = lrelu(o.x); o.y = lrelu(o.y); o.z = lrelu(o.z); o.w = lrelu(o.w); }
    ((float4*)out)[(size_t)node * TPN + cg] = o;
}

// ---------------- pooling ----------------
__global__ void k_pool_sum(const float* __restrict__ x, const int* __restrict__ batch,
                           float* __restrict__ out, int n) {
    int idx = blockIdx.x * blockDim.x + threadIdx.x;
    if (idx >= n * 16) return;
    int nn = idx / 16, cg = idx % 16;
    int g = __ldg(batch + nn);
    float4 v = ((const float4*)x)[idx];
    atomicAdd((float4*)out + (size_t)g * 16 + cg, v);
}
__global__ void k_pool_cnt(const int* __restrict__ batch, float* cnt, int n) {
    int i = blockIdx.x * blockDim.x + threadIdx.x;
    if (i < n) atomicAdd(&cnt[batch[i]], 1.0f);
}
__global__ void k_pool_div(float* out, const float* cnt, int total) {
    int i = blockIdx.x * blockDim.x + threadIdx.x;
    if (i >= total) return;
    int g = i / 64;
    out[i] /= fmaxf(cnt[g], 1.0f);
}

// ---------------- host ----------------
static inline int GRID(long long t) { return (int)((t + 255) / 256); }

extern "C" void kernel_launch(void* const* d_in, const int* in_sizes, int n_in,
                              void* d_out, int out_size) {
    const float* x     = (const float*)d_in[0];
    const int*   ei    = (const int*)d_in[1];
    const int*   batch = (const int*)d_in[2];
    const int n = in_sizes[0] / 16;
    const int E = in_sizes[1] / 2;
    const int* rowp = ei;
    const int* colp = ei + E;

    const float* gcn_w[4] = {(const float*)d_in[3], (const float*)d_in[7],
                             (const float*)d_in[11], (const float*)d_in[15]};
    const float* gcn_b[4] = {(const float*)d_in[4], (const float*)d_in[8],
                             (const float*)d_in[12], (const float*)d_in[16]};
    const float* bn_g[4]  = {(const float*)d_in[5], (const float*)d_in[9],
                             (const float*)d_in[13], (const float*)d_in[17]};
    const float* bn_b[4]  = {(const float*)d_in[6], (const float*)d_in[10],
                             (const float*)d_in[14], (const float*)d_in[18]};
    const float* gat_w0    = (const float*)d_in[19];
    const float* gat_asrc0 = (const float*)d_in[20];
    const float* gat_adst0 = (const float*)d_in[21];
    const float* gat_b0    = (const float*)d_in[22];
    const float* gat_w2    = (const float*)d_in[23];
    const float* gat_asrc2 = (const float*)d_in[24];
    const float* gat_adst2 = (const float*)d_in[25];
    const float* gat_b2    = (const float*)d_in[26];

    float *A, *B, *C, *dis, *ss, *sd, *mean, *sq, *scale, *shift, *cnt;
    int *deg, *rowptr, *cursor, *csr, *blksum;
    cudaGetSymbolAddress((void**)&A, g_A);
    cudaGetSymbolAddress((void**)&B, g_B);
    cudaGetSymbolAddress((void**)&C, g_C);
    cudaGetSymbolAddress((void**)&dis, g_dis);
    cudaGetSymbolAddress((void**)&deg, g_deg);
    cudaGetSymbolAddress((void**)&rowptr, g_rowptr);
    cudaGetSymbolAddress((void**)&cursor, g_cursor);
    cudaGetSymbolAddress((void**)&csr, g_csr);
    cudaGetSymbolAddress((void**)&blksum, g_blksum);
    cudaGetSymbolAddress((void**)&ss, g_ss);
    cudaGetSymbolAddress((void**)&sd, g_sd);
    cudaGetSymbolAddress((void**)&mean, g_mean);
    cudaGetSymbolAddress((void**)&sq, g_sq);
    cudaGetSymbolAddress((void**)&scale, g_scale);
    cudaGetSymbolAddress((void**)&shift, g_shift);
    cudaGetSymbolAddress((void**)&cnt, g_cnt);
    float* out = (float*)d_out;

    // ---- build CSR (by destination) + dis ----
    const int nb = (n + SCAN_CHUNK - 1) / SCAN_CHUNK;
    k_deg_zero<<<GRID(n), 256>>>(deg, n);
    k_deg_count<<<GRID(E), 256>>>(colp, deg, E);
    k_dis<<<GRID(n), 256>>>(deg, dis, n);
    k_scan1<<<nb, SCAN_CHUNK>>>(deg, blksum, n);
    k_scan2<<<1, 32>>>(blksum, nb, rowptr + n);
    k_scan3<<<nb, SCAN_CHUNK>>>(deg, blksum, rowptr, cursor, n);
    k_csr_fill<<<GRID(E), 256>>>(rowp, colp, cursor, csr, E);

    // ----- layer 0: GCN 16->64, BN, GAT(64)+residual, lrelu -----
    k_linear<16, 64><<<(n + 63) / 64, 256>>>(x, gcn_w[0], B, n);
    k_gcn_gather<64><<<(n + 15) / 16, 256>>>(rowptr, csr, dis, B, gcn_b[0], C, n);
    k_zero2<<<1, 128>>>(mean, sq, 128);
    k_bn_partial<64><<<(n + 63) / 64, 256>>>(C, mean, sq, n);
    k_bn_final<64><<<1, 64>>>(mean, sq, bn_g[0], bn_b[0], scale, shift, n);
    k_bn_apply<64, false><<<GRID((long long)n * 16), 256>>>(C, scale, shift, A, n);
    k_linear<64, 64><<<(n + 63) / 64, 256>>>(A, gat_w0, B, n);
    k_gat_scores<64, 4><<<(n + 3) / 4, 128>>>(B, gat_asrc0, gat_adst0, ss, sd, n);
    k_gat_fused<64, 4, true><<<(n + 15) / 16, 256>>>(rowptr, csr, ss, sd, B, gat_b0, A, A, n);

    // ----- layer 1: GCN 64->128, BN, lrelu -----
    k_linear<64, 128><<<(n + 31) / 32, 256>>>(A, gcn_w[1], B, n);
    k_gcn_gather<128><<<(n + 7) / 8, 256>>>(rowptr, csr, dis, B, gcn_b[1], C, n);
    k_zero2<<<1, 128>>>(mean, sq, 128);
    k_bn_partial<128><<<(n + 63) / 64, 256>>>(C, mean, sq, n);
    k_bn_final<128><<<1, 128>>>(mean, sq, bn_g[1], bn_b[1], scale, shift, n);
    k_bn_apply<128, true><<<GRID((long long)n * 32), 256>>>(C, scale, shift, A, n);

    // ----- layer 2: GCN 128->128, BN, GAT(128)+residual, lrelu -----
    k_linear<128, 128><<<(n + 31) / 32, 256>>>(A, gcn_w[2], B, n);
    k_gcn_gather<128><<<(n + 7) / 8, 256>>>(rowptr, csr, dis, B, gcn_b[2], C, n);
    k_zero2<<<1, 128>>>(mean, sq, 128);
    k_bn_partial<128><<<(n + 63) / 64, 256>>>(C, mean, sq, n);
    k_bn_final<128><<<1, 128>>>(mean, sq, bn_g[2], bn_b[2], scale, shift, n);
    k_bn_apply<128, false><<<GRID((long long)n * 32), 256>>>(C, scale, shift, A, n);
    k_linear<128, 128><<<(n + 31) / 32, 256>>>(A, gat_w2, B, n);
    k_gat_scores<128, 4><<<(n + 3) / 4, 128>>>(B, gat_asrc2, gat_adst2, ss, sd, n);
    k_gat_fused<128, 4, true><<<(n + 7) / 8, 256>>>(rowptr, csr, ss, sd, B, gat_b2, A, A, n);

    // ----- layer 3: GCN 128->64, BN (no relu, no GAT) -----
    k_linear<128, 64><<<(n + 63) / 64, 256>>>(A, gcn_w[3], B, n);
    k_gcn_gather<64><<<(n + 15) / 16, 256>>>(rowptr, csr, dis, B, gcn_b[3], C, n);
    k_zero2<<<1, 128>>>(mean, sq, 128);
    k_bn_partial<64><<<(n + 63) / 64, 256>>>(C, mean, sq, n);
    k_bn_final<64><<<1, 64>>>(mean, sq, bn_g[3], bn_b[3], scale, shift, n);
    k_bn_apply<64, false><<<GRID((long long)n * 16), 256>>>(C, scale, shift, A, n);

    // ----- global mean pool -----
    const int G = out_size / 64;
    k_set_val<<<GRID(out_size), 256>>>(out, 0.0f, out_size);
    k_set_val<<<GRID(G), 256>>>(cnt, 0.0f, G);
    k_pool_sum<<<GRID((long long)n * 16), 256>>>(A, batch, out, n);
    k_pool_cnt<<<GRID(n), 256>>>(batch, cnt, n);
    k_pool_div<<<GRID(out_size), 256>>>(out, cnt, out_size);
}

// round 3
// speedup vs baseline: 2.6035x; 1.6205x over previous
#include <cuda_runtime.h>
#include <cuda_bf16.h>
#include <math.h>

#define NMAX 100000
#define EMAX 1600000
#define GMAX 256
#define HEADSN 4
#define SCAN_CHUNK 512

// ---------------- scratch ----------------
__device__ __align__(16) float g_A[(size_t)NMAX * 128];
__device__ __align__(16) float g_B[(size_t)NMAX * 128];
__device__ __align__(16) float g_C[(size_t)NMAX * 128];
__device__ __align__(16) float g_dis[NMAX];
__device__ __align__(16) int   g_deg[NMAX];
__device__ __align__(16) int   g_rowptr[NMAX + 1];
__device__ __align__(16) int   g_cursor[NMAX];
__device__ __align__(16) int   g_csr[EMAX];
__device__ __align__(16) int   g_blksum[1024];
__device__ __align__(16) float g_ss[NMAX * HEADSN];
__device__ __align__(16) float g_sd[NMAX * HEADSN];
__device__ __align__(16) float g_m[NMAX * HEADSN];
__device__ __align__(16) float g_ws[NMAX * HEADSN];
__device__ __align__(16) float g_mean[128];
__device__ __align__(16) float g_sq[128];
__device__ __align__(16) float g_scale[128];
__device__ __align__(16) float g_shift[128];
__device__ __align__(16) float g_cnt[GMAX];
__device__ __align__(16) float g_zero[128];

__device__ __forceinline__ float lrelu(float v) { return v > 0.f ? v : 0.2f * v; }
__device__ __forceinline__ unsigned f2tf(float f) {
    unsigned u; asm("cvt.rna.tf32.f32 %0, %1;" : "=r"(u) : "f"(f)); return u;
}

// ---------------- utility ----------------
__global__ void k_set_val(float* p, float v, int n) {
    int i = blockIdx.x * blockDim.x + threadIdx.x;
    if (i < n) p[i] = v;
}
__global__ void k_zero2(float* a, float* b, int n) {
    int i = blockIdx.x * blockDim.x + threadIdx.x;
    if (i < n) { a[i] = 0.f; b[i] = 0.f; }
}
__global__ void k_deg_zero(int* deg, int n) {
    int i = blockIdx.x * blockDim.x + threadIdx.x;
    if (i < n) deg[i] = 0;
}
__global__ void k_deg_count(const int* __restrict__ colp, int* deg, int E) {
    int i = blockIdx.x * blockDim.x + threadIdx.x;
    if (i < E) atomicAdd(&deg[colp[i]], 1);
}
__global__ void k_dis(const int* __restrict__ deg, float* dis, int n) {
    int i = blockIdx.x * blockDim.x + threadIdx.x;
    if (i < n) dis[i] = rsqrtf(1.0f + (float)deg[i]);
}

// ---------------- scan ----------------
__global__ void k_scan1(const int* __restrict__ deg, int* blksum, int n) {
    __shared__ int sh[SCAN_CHUNK];
    int i = blockIdx.x * SCAN_CHUNK + threadIdx.x;
    sh[threadIdx.x] = (i < n) ? deg[i] : 0;
    __syncthreads();
    for (int off = SCAN_CHUNK / 2; off > 0; off >>= 1) {
        if (threadIdx.x < off) sh[threadIdx.x] += sh[threadIdx.x + off];
        __syncthreads();
    }
    if (threadIdx.x == 0) blksum[blockIdx.x] = sh[0];
}
__global__ void k_scan2(int* blksum, int nb, int* rowptr_n) {
    if (threadIdx.x == 0) {
        int acc = 0;
        for (int b = 0; b < nb; ++b) { int v = blksum[b]; blksum[b] = acc; acc += v; }
        *rowptr_n = acc;
    }
}
__global__ void k_scan3(const int* __restrict__ deg, const int* __restrict__ blksum,
                        int* rowptr, int* cursor, int n) {
    __shared__ int sh[SCAN_CHUNK];
    int i = blockIdx.x * SCAN_CHUNK + threadIdx.x;
    int v = (i < n) ? deg[i] : 0;
    sh[threadIdx.x] = v;
    __syncthreads();
    for (int off = 1; off < SCAN_CHUNK; off <<= 1) {
        int t = (threadIdx.x >= off) ? sh[threadIdx.x - off] : 0;
        __syncthreads();
        sh[threadIdx.x] += t;
        __syncthreads();
    }
    if (i < n) {
        int excl = blksum[blockIdx.x] + sh[threadIdx.x] - v;
        rowptr[i] = excl;
        cursor[i] = excl;
    }
}
__global__ void k_csr_fill(const int* __restrict__ rowp, const int* __restrict__ colp,
                           int* cursor, int* csr, int E) {
    int e = blockIdx.x * blockDim.x + threadIdx.x;
    if (e >= E) return;
    int c = colp[e];
    int pos = atomicAdd(&cursor[c], 1);
    csr[pos] = rowp[e];
}

// ---------------- TF32 tensor-core GEMM: out = X @ W (+bias) ----------------
// X [n, DIN] row-major, W [DIN, DOUT] row-major, out [n, DOUT].
template <int DIN, int DOUT, bool BIAS>
__global__ void k_gemm(const float* __restrict__ X, const float* __restrict__ W,
                       const float* __restrict__ bias, float* __restrict__ out, int n) {
    constexpr int NT = (DOUT >= 128) ? 64 : 128;   // node tile
    constexpr int KT = (DIN < 32) ? DIN : 32;      // k tile
    constexpr int NW = NT / 16;                    // node subtiles (warps along nodes)
    constexpr int CW = DOUT / 64;                  // col groups
    static_assert(NW * CW == 8, "8 warps");
    constexpr int XS = KT + 4;
    constexpr int WS = DOUT + 4;
    __shared__ unsigned Xs[NT * XS];
    __shared__ unsigned Ws[KT * WS];

    const int tid = threadIdx.x;
    const int wid = tid >> 5, lane = tid & 31;
    const int g = lane >> 2, tig = lane & 3;
    const int nsub = wid % NW, cgp = wid / NW;
    const int base = blockIdx.x * NT;

    float acc[8][4];
#pragma unroll
    for (int i = 0; i < 8; ++i)
#pragma unroll
        for (int j = 0; j < 4; ++j) acc[i][j] = 0.f;

    for (int kt = 0; kt < DIN; kt += KT) {
        for (int i = tid; i < NT * (KT / 4); i += 256) {
            int r = i / (KT / 4), c = i % (KT / 4);
            int node = base + r;
            float4 v = make_float4(0.f, 0.f, 0.f, 0.f);
            if (node < n) v = ((const float4*)X)[(size_t)node * (DIN / 4) + kt / 4 + c];
            unsigned* d = &Xs[r * XS + c * 4];
            d[0] = f2tf(v.x); d[1] = f2tf(v.y); d[2] = f2tf(v.z); d[3] = f2tf(v.w);
        }
        for (int i = tid; i < KT * (DOUT / 4); i += 256) {
            int r = i / (DOUT / 4), c = i % (DOUT / 4);
            float4 v = ((const float4*)W)[(size_t)(kt + r) * (DOUT / 4) + c];
            unsigned* d = &Ws[r * WS + c * 4];
            d[0] = f2tf(v.x); d[1] = f2tf(v.y); d[2] = f2tf(v.z); d[3] = f2tf(v.w);
        }
        __syncthreads();
#pragma unroll
        for (int ks = 0; ks < KT; ks += 8) {
            int r0 = nsub * 16 + g;
            unsigned a0 = Xs[r0 * XS + ks + tig];
            unsigned a1 = Xs[(r0 + 8) * XS + ks + tig];
            unsigned a2 = Xs[r0 * XS + ks + tig + 4];
            unsigned a3 = Xs[(r0 + 8) * XS + ks + tig + 4];
#pragma unroll
            for (int nb = 0; nb < 8; ++nb) {
                int col = cgp * 64 + nb * 8 + g;
                unsigned b0 = Ws[(ks + tig) * WS + col];
                unsigned b1 = Ws[(ks + tig + 4) * WS + col];
                asm volatile(
                    "mma.sync.aligned.m16n8k8.row.col.f32.tf32.tf32.f32 "
                    "{%0,%1,%2,%3}, {%4,%5,%6,%7}, {%8,%9}, {%0,%1,%2,%3};"
                    : "+f"(acc[nb][0]), "+f"(acc[nb][1]), "+f"(acc[nb][2]), "+f"(acc[nb][3])
                    : "r"(a0), "r"(a1), "r"(a2), "r"(a3), "r"(b0), "r"(b1));
            }
        }
        __syncthreads();
    }
    int node0 = base + nsub * 16 + g;
#pragma unroll
    for (int nb = 0; nb < 8; ++nb) {
        int col = cgp * 64 + nb * 8 + 2 * tig;
        float b0 = 0.f, b1 = 0.f;
        if (BIAS) { b0 = __ldg(bias + col); b1 = __ldg(bias + col + 1); }
        if (node0 < n) {
            float2 v = make_float2(acc[nb][0] + b0, acc[nb][1] + b1);
            *(float2*)(out + (size_t)node0 * DOUT + col) = v;
        }
        if (node0 + 8 < n) {
            float2 v = make_float2(acc[nb][2] + b0, acc[nb][3] + b1);
            *(float2*)(out + (size_t)(node0 + 8) * DOUT + col) = v;
        }
    }
}

// ---------------- GCN gather (shuffle-broadcast, atomic-free) ----------------
// out[c] = bias + h[c]*dis[c]^2 + sum_{r in N(c)} h[r]*dis[r]*dis[c]
template <int TPN>  // TPN = D/4 lanes per node
__global__ void k_gcn_gather(const int* __restrict__ rowptr, const int* __restrict__ csr,
                             const float* __restrict__ dis, const float* __restrict__ h,
                             const float* __restrict__ bias, float* __restrict__ out, int n) {
    int t = blockIdx.x * 256 + threadIdx.x;
    int node = t / TPN, sub = t % TPN;
    if (node >= n) return;
    unsigned smask = (TPN == 32) ? 0xffffffffu
                   : (((1u << TPN) - 1u) << ((threadIdx.x & 31) & ~(TPN - 1)));
    float dc = __ldg(dis + node);
    float4 acc = __ldg((const float4*)bias + sub);
    {
        float4 hv = __ldg((const float4*)h + (size_t)node * TPN + sub);
        float w = dc * dc;
        acc.x += hv.x * w; acc.y += hv.y * w; acc.z += hv.z * w; acc.w += hv.w * w;
    }
    int s0 = __ldg(rowptr + node), s1 = __ldg(rowptr + node + 1);
    for (int bjs = s0; bjs < s1; bjs += TPN) {
        int j = bjs + sub;
        int r = 0; float w = 0.f;
        if (j < s1) { r = __ldg(csr + j); w = __ldg(dis + r) * dc; }
#pragma unroll
        for (int tt = 0; tt < TPN; ++tt) {
            if (bjs + tt >= s1) break;
            int rr = __shfl_sync(smask, r, tt, TPN);
            float ww = __shfl_sync(smask, w, tt, TPN);
            float4 v = __ldg((const float4*)h + (size_t)rr * TPN + sub);
            acc.x += v.x * ww; acc.y += v.y * ww; acc.z += v.z * ww; acc.w += v.w * ww;
        }
    }
    ((float4*)out)[(size_t)node * TPN + sub] = acc;
}

// ---------------- BatchNorm ----------------
template <int DOUT>
__global__ void k_bn_partial(const float* __restrict__ src, float* mean, float* sq, int n) {
    constexpr int LPC = 256 / DOUT;
    constexpr int NPB = 64;
    int col = threadIdx.x % DOUT, sub = threadIdx.x / DOUT;
    int base = blockIdx.x * NPB;
    int end = base + NPB; if (end > n) end = n;
    float s = 0.f, q = 0.f;
    for (int nn = base + sub; nn < end; nn += LPC) {
        float v = src[(size_t)nn * DOUT + col];
        s += v; q += v * v;
    }
    __shared__ float sh[512];
    sh[threadIdx.x] = s; sh[256 + threadIdx.x] = q;
    __syncthreads();
    if (sub == 0) {
        for (int k = 1; k < LPC; ++k) { s += sh[k * DOUT + col]; q += sh[256 + k * DOUT + col]; }
        atomicAdd(mean + col, s);
        atomicAdd(sq + col, q);
    }
}
template <int DOUT>
__global__ void k_bn_final(const float* mean, const float* sq,
                           const float* __restrict__ g, const float* __restrict__ b,
                           float* scale, float* shift, int n) {
    int c = threadIdx.x;
    if (c >= DOUT) return;
    float inv = 1.0f / (float)n;
    float mu = mean[c] * inv;
    float var = sq[c] * inv - mu * mu;
    float sc = g[c] * rsqrtf(var + 1e-5f);
    scale[c] = sc;
    shift[c] = b[c] - mu * sc;
}
template <int DOUT, bool RELU>
__global__ void k_bn_apply(const float* __restrict__ src, const float* scale,
                           const float* shift, float* __restrict__ dst, int n) {
    constexpr int TPN = DOUT / 4;
    int idx = blockIdx.x * blockDim.x + threadIdx.x;
    if (idx >= n * TPN) return;
    int cg = idx % TPN;
    float4 v = ((const float4*)src)[idx];
    float4 sc = ((const float4*)scale)[cg];
    float4 sh = ((const float4*)shift)[cg];
    v.x = v.x * sc.x + sh.x; v.y = v.y * sc.y + sh.y;
    v.z = v.z * sc.z + sh.z; v.w = v.w * sc.w + sh.w;
    if (RELU) { v.x = lrelu(v.x); v.y = lrelu(v.y); v.z = lrelu(v.z); v.w = lrelu(v.w); }
    ((float4*)dst)[idx] = v;
}

// ---------------- GAT ----------------
template <int D, int H>
__global__ void k_gat_scores(const float* __restrict__ h2,
                             const float* __restrict__ a_src, const float* __restrict__ a_dst,
                             float* __restrict__ ss, float* __restrict__ sd, int n) {
    constexpr int C  = D / H;
    constexpr int L  = D / 4;
    constexpr int GP = C / 4;
    int warp = (blockIdx.x * blockDim.x + threadIdx.x) >> 5;
    int lane = threadIdx.x & 31;
    if (warp >= n) return;
    float ps = 0.f, pd = 0.f;
    int head = 0;
    if (lane < L) {
        float4 v = ((const float4*)h2)[(size_t)warp * L + lane];
        head = lane / GP;
        int o = head * C + (lane % GP) * 4;
        ps = v.x * __ldg(a_src + o) + v.y * __ldg(a_src + o + 1)
           + v.z * __ldg(a_src + o + 2) + v.w * __ldg(a_src + o + 3);
        pd = v.x * __ldg(a_dst + o) + v.y * __ldg(a_dst + o + 1)
           + v.z * __ldg(a_dst + o + 2) + v.w * __ldg(a_dst + o + 3);
    }
#pragma unroll
    for (int off = GP / 2; off > 0; off >>= 1) {
        ps += __shfl_xor_sync(0xffffffff, ps, off);
        pd += __shfl_xor_sync(0xffffffff, pd, off);
    }
    if (lane < L && (lane % GP) == 0) {
        ss[(size_t)warp * H + head] = ps;
        sd[(size_t)warp * H + head] = pd;
    }
}

#define NEG_BIG -1e30f
__device__ __forceinline__ void online_upd(float& m, float& s, float e) {
    float nm = fmaxf(m, e);
    s = s * __expf(m - nm) + __expf(e - nm);
    m = nm;
}
__device__ __forceinline__ void online_comb(float& m, float& s, float m2, float s2) {
    float nm = fmaxf(m, m2);
    s = s * __expf(m - nm) + s2 * __expf(m2 - nm);
    m = nm;
}

// warp per node: online softmax denominators over neighbors + self loop
__global__ void k_gat_softmax(const int* __restrict__ rowptr, const int* __restrict__ csr,
                              const float* __restrict__ ss, const float* __restrict__ sd,
                              float* __restrict__ mout, float* __restrict__ wsout, int n) {
    int warp = (blockIdx.x * blockDim.x + threadIdx.x) >> 5;
    int lane = threadIdx.x & 31;
    if (warp >= n) return;
    float4 sdv = ((const float4*)sd)[warp];
    float4 m = make_float4(NEG_BIG, NEG_BIG, NEG_BIG, NEG_BIG);
    float4 s = make_float4(0.f, 0.f, 0.f, 0.f);
    if (lane == 0) {
        float4 e = ((const float4*)ss)[warp];
        m.x = lrelu(e.x + sdv.x); m.y = lrelu(e.y + sdv.y);
        m.z = lrelu(e.z + sdv.z); m.w = lrelu(e.w + sdv.w);
        s = make_float4(1.f, 1.f, 1.f, 1.f);
    }
    int s0 = __ldg(rowptr + warp), s1 = __ldg(rowptr + warp + 1);
    for (int j = s0 + lane; j < s1; j += 32) {
        int r = __ldg(csr + j);
        float4 e = __ldg((const float4*)ss + r);
        online_upd(m.x, s.x, lrelu(e.x + sdv.x));
        online_upd(m.y, s.y, lrelu(e.y + sdv.y));
        online_upd(m.z, s.z, lrelu(e.z + sdv.z));
        online_upd(m.w, s.w, lrelu(e.w + sdv.w));
    }
#pragma unroll
    for (int off = 16; off > 0; off >>= 1) {
        float m2x = __shfl_xor_sync(0xffffffff, m.x, off);
        float m2y = __shfl_xor_sync(0xffffffff, m.y, off);
        float m2z = __shfl_xor_sync(0xffffffff, m.z, off);
        float m2w = __shfl_xor_sync(0xffffffff, m.w, off);
        float s2x = __shfl_xor_sync(0xffffffff, s.x, off);
        float s2y = __shfl_xor_sync(0xffffffff, s.y, off);
        float s2z = __shfl_xor_sync(0xffffffff, s.z, off);
        float s2w = __shfl_xor_sync(0xffffffff, s.w, off);
        online_comb(m.x, s.x, m2x, s2x);
        online_comb(m.y, s.y, m2y, s2y);
        online_comb(m.z, s.z, m2z, s2z);
        online_comb(m.w, s.w, m2w, s2w);
    }
    if (lane == 0) {
        ((float4*)mout)[warp] = m;
        ((float4*)wsout)[warp] = s;
    }
}

// single fused pass: weighted gather + bias + residual (+lrelu)
template <int TPN, int H, bool RELU>  // TPN = D/4
__global__ void k_gat_fused(const int* __restrict__ rowptr, const int* __restrict__ csr,
                            const float* __restrict__ ss, const float* __restrict__ sd,
                            const float* __restrict__ m_, const float* __restrict__ ws_,
                            const float* __restrict__ h2, const float* __restrict__ bias,
                            const float* __restrict__ res, float* __restrict__ out, int n) {
    constexpr int C = TPN * 4 / H;   // channels per head
    int t = blockIdx.x * 256 + threadIdx.x;
    int node = t / TPN, sub = t % TPN;
    if (node >= n) return;
    unsigned smask = (TPN == 32) ? 0xffffffffu
                   : (((1u << TPN) - 1u) << ((threadIdx.x & 31) & ~(TPN - 1)));
    int head = (sub * 4) / C;
    float sdv = __ldg(sd + (size_t)node * H + head);
    float m   = __ldg(m_ + (size_t)node * H + head);
    float inv = 1.0f / __ldg(ws_ + (size_t)node * H + head);

    float wsf = __expf(lrelu(__ldg(ss + (size_t)node * H + head) + sdv) - m);
    float4 acc = __ldg((const float4*)h2 + (size_t)node * TPN + sub);
    acc.x *= wsf; acc.y *= wsf; acc.z *= wsf; acc.w *= wsf;

    int s0 = __ldg(rowptr + node), s1 = __ldg(rowptr + node + 1);
    for (int bjs = s0; bjs < s1; bjs += TPN) {
        int j = bjs + sub;
        int r = 0;
        if (j < s1) r = __ldg(csr + j);
#pragma unroll
        for (int tt = 0; tt < TPN; ++tt) {
            if (bjs + tt >= s1) break;
            int rr = __shfl_sync(smask, r, tt, TPN);
            float e = lrelu(__ldg(ss + (size_t)rr * H + head) + sdv);
            float w = __expf(e - m);
            float4 v = __ldg((const float4*)h2 + (size_t)rr * TPN + sub);
            acc.x += v.x * w; acc.y += v.y * w; acc.z += v.z * w; acc.w += v.w * w;
        }
    }
    float4 bv = __ldg((const float4*)bias + sub);
    float4 xv = __ldg((const float4*)res + (size_t)node * TPN + sub);
    float4 o;
    o.x = acc.x * inv + bv.x + xv.x;
    o.y = acc.y * inv + bv.y + xv.y;
    o.z = acc.z * inv + bv.z + xv.z;
    o.w = acc.w * inv + bv.w + xv.w;
    if (RELU) { o.x = lrelu(o.x); o.y = lrelu(o.y); o.z = lrelu(o.z); o.w = lrelu(o.w); }
    ((float4*)out)[(size_t)node * TPN + sub] = o;
}

// ---------------- pooling ----------------
__global__ void k_pool_sum(const float* __restrict__ x, const int* __restrict__ batch,
                           float* __restrict__ out, int n) {
    int idx = blockIdx.x * blockDim.x + threadIdx.x;
    if (idx >= n * 16) return;
    int nn = idx / 16, cg = idx % 16;
    int g = __ldg(batch + nn);
    float4 v = ((const float4*)x)[idx];
    atomicAdd((float4*)out + (size_t)g * 16 + cg, v);
}
__global__ void k_pool_cnt(const int* __restrict__ batch, float* cnt, int n) {
    int i = blockIdx.x * blockDim.x + threadIdx.x;
    if (i < n) atomicAdd(&cnt[batch[i]], 1.0f);
}
__global__ void k_pool_div(float* out, const float* cnt, int total) {
    int i = blockIdx.x * blockDim.x + threadIdx.x;
    if (i >= total) return;
    int g = i / 64;
    out[i] /= fmaxf(cnt[g], 1.0f);
}

// ---------------- host ----------------
static inline int GRID(long long t) { return (int)((t + 255) / 256); }

extern "C" void kernel_launch(void* const* d_in, const int* in_sizes, int n_in,
                              void* d_out, int out_size) {
    const float* x     = (const float*)d_in[0];
    const int*   ei    = (const int*)d_in[1];
    const int*   batch = (const int*)d_in[2];
    const int n = in_sizes[0] / 16;
    const int E = in_sizes[1] / 2;
    const int* rowp = ei;
    const int* colp = ei + E;

    const float* gcn_w[4] = {(const float*)d_in[3], (const float*)d_in[7],
                             (const float*)d_in[11], (const float*)d_in[15]};
    const float* gcn_b[4] = {(const float*)d_in[4], (const float*)d_in[8],
                             (const float*)d_in[12], (const float*)d_in[16]};
    const float* bn_g[4]  = {(const float*)d_in[5], (const float*)d_in[9],
                             (const float*)d_in[13], (const float*)d_in[17]};
    const float* bn_b[4]  = {(const float*)d_in[6], (const float*)d_in[10],
                             (const float*)d_in[14], (const float*)d_in[18]};
    const float* gat_w0    = (const float*)d_in[19];
    const float* gat_asrc0 = (const float*)d_in[20];
    const float* gat_adst0 = (const float*)d_in[21];
    const float* gat_b0    = (const float*)d_in[22];
    const float* gat_w2    = (const float*)d_in[23];
    const float* gat_asrc2 = (const float*)d_in[24];
    const float* gat_adst2 = (const float*)d_in[25];
    const float* gat_b2    = (const float*)d_in[26];

    float *A, *B, *C, *dis, *ss, *sd, *mM, *wsum, *mean, *sq, *scale, *shift, *cnt, *zbuf;
    int *deg, *rowptr, *cursor, *csr, *blksum;
    cudaGetSymbolAddress((void**)&A, g_A);
    cudaGetSymbolAddress((void**)&B, g_B);
    cudaGetSymbolAddress((void**)&C, g_C);
    cudaGetSymbolAddress((void**)&dis, g_dis);
    cudaGetSymbolAddress((void**)&deg, g_deg);
    cudaGetSymbolAddress((void**)&rowptr, g_rowptr);
    cudaGetSymbolAddress((void**)&cursor, g_cursor);
    cudaGetSymbolAddress((void**)&csr, g_csr);
    cudaGetSymbolAddress((void**)&blksum, g_blksum);
    cudaGetSymbolAddress((void**)&ss, g_ss);
    cudaGetSymbolAddress((void**)&sd, g_sd);
    cudaGetSymbolAddress((void**)&mM, g_m);
    cudaGetSymbolAddress((void**)&wsum, g_ws);
    cudaGetSymbolAddress((void**)&mean, g_mean);
    cudaGetSymbolAddress((void**)&sq, g_sq);
    cudaGetSymbolAddress((void**)&scale, g_scale);
    cudaGetSymbolAddress((void**)&shift, g_shift);
    cudaGetSymbolAddress((void**)&cnt, g_cnt);
    cudaGetSymbolAddress((void**)&zbuf, g_zero);
    float* out = (float*)d_out;

    // ---- CSR build + dis + zero-bias ----
    const int nb = (n + SCAN_CHUNK - 1) / SCAN_CHUNK;
    k_set_val<<<1, 128>>>(zbuf, 0.0f, 128);
    k_deg_zero<<<GRID(n), 256>>>(deg, n);
    k_deg_count<<<GRID(E), 256>>>(colp, deg, E);
    k_dis<<<GRID(n), 256>>>(deg, dis, n);
    k_scan1<<<nb, SCAN_CHUNK>>>(deg, blksum, n);
    k_scan2<<<1, 32>>>(blksum, nb, rowptr + n);
    k_scan3<<<nb, SCAN_CHUNK>>>(deg, blksum, rowptr, cursor, n);
    k_csr_fill<<<GRID(E), 256>>>(rowp, colp, cursor, csr, E);

    // ----- layer 0: gather@16 -> gemm 16->64 (+b) -> BN -> GAT(64)+res, lrelu -----
    k_gcn_gather<4><<<(n + 63) / 64, 256>>>(rowptr, csr, dis, x, zbuf, C, n);
    k_gemm<16, 64, true><<<(n + 127) / 128, 256>>>(C, gcn_w[0], gcn_b[0], B, n);
    k_zero2<<<1, 128>>>(mean, sq, 128);
    k_bn_partial<64><<<(n + 63) / 64, 256>>>(B, mean, sq, n);
    k_bn_final<64><<<1, 64>>>(mean, sq, bn_g[0], bn_b[0], scale, shift, n);
    k_bn_apply<64, false><<<GRID((long long)n * 16), 256>>>(B, scale, shift, A, n);
    k_gemm<64, 64, false><<<(n + 127) / 128, 256>>>(A, gat_w0, zbuf, B, n);
    k_gat_scores<64, 4><<<(n + 3) / 4, 128>>>(B, gat_asrc0, gat_adst0, ss, sd, n);
    k_gat_softmax<<<(n + 7) / 8, 256>>>(rowptr, csr, ss, sd, mM, wsum, n);
    k_gat_fused<16, 4, true><<<(n + 15) / 16, 256>>>(rowptr, csr, ss, sd, mM, wsum, B, gat_b0, A, A, n);

    // ----- layer 1: gather@64 -> gemm 64->128 (+b) -> BN + lrelu -----
    k_gcn_gather<16><<<(n + 15) / 16, 256>>>(rowptr, csr, dis, A, zbuf, C, n);
    k_gemm<64, 128, true><<<(n + 63) / 64, 256>>>(C, gcn_w[1], gcn_b[1], B, n);
    k_zero2<<<1, 128>>>(mean, sq, 128);
    k_bn_partial<128><<<(n + 63) / 64, 256>>>(B, mean, sq, n);
    k_bn_final<128><<<1, 128>>>(mean, sq, bn_g[1], bn_b[1], scale, shift, n);
    k_bn_apply<128, true><<<GRID((long long)n * 32), 256>>>(B, scale, shift, A, n);

    // ----- layer 2: gather@128 -> gemm 128->128 (+b) -> BN -> GAT(128)+res, lrelu -----
    k_gcn_gather<32><<<(n + 7) / 8, 256>>>(rowptr, csr, dis, A, zbuf, C, n);
    k_gemm<128, 128, true><<<(n + 63) / 64, 256>>>(C, gcn_w[2], gcn_b[2], B, n);
    k_zero2<<<1, 128>>>(mean, sq, 128);
    k_bn_partial<128><<<(n + 63) / 64, 256>>>(B, mean, sq, n);
    k_bn_final<128><<<1, 128>>>(mean, sq, bn_g[2], bn_b[2], scale, shift, n);
    k_bn_apply<128, false><<<GRID((long long)n * 32), 256>>>(B, scale, shift, A, n);
    k_gemm<128, 128, false><<<(n + 63) / 64, 256>>>(A, gat_w2, zbuf, B, n);
    k_gat_scores<128, 4><<<(n + 3) / 4, 128>>>(B, gat_asrc2, gat_adst2, ss, sd, n);
    k_gat_softmax<<<(n + 7) / 8, 256>>>(rowptr, csr, ss, sd, mM, wsum, n);
    k_gat_fused<32, 4, true><<<(n + 7) / 8, 256>>>(rowptr, csr, ss, sd, mM, wsum, B, gat_b2, A, A, n);

    // ----- layer 3: gemm 128->64 -> gather@64 (+b after agg) -> BN -----
    k_gemm<128, 64, false><<<(n + 127) / 128, 256>>>(A, gcn_w[3], zbuf, B, n);
    k_gcn_gather<16><<<(n + 15) / 16, 256>>>(rowptr, csr, dis, B, gcn_b[3], C, n);
    k_zero2<<<1, 128>>>(mean, sq, 128);
    k_bn_partial<64><<<(n + 63) / 64, 256>>>(C, mean, sq, n);
    k_bn_final<64><<<1, 64>>>(mean, sq, bn_g[3], bn_b[3], scale, shift, n);
    k_bn_apply<64, false><<<GRID((long long)n * 16), 256>>>(C, scale, shift, A, n);

    // ----- global mean pool -----
    const int G = out_size / 64;
    k_set_val<<<GRID(out_size), 256>>>(out, 0.0f, out_size);
    k_set_val<<<GRID(G), 256>>>(cnt, 0.0f, G);
    k_pool_sum<<<GRID((long long)n * 16), 256>>>(A, batch, out, n);
    k_pool_cnt<<<GRID(n), 256>>>(batch, cnt, n);
    k_pool_div<<<GRID(out_size), 256>>>(out, cnt, out_size);
}